// round 9
// baseline (speedup 1.0000x reference)
#include <cuda_runtime.h>
#include <math_constants.h>
#include <cstdint>

// ChamferLoss: B=4, N=8192, M=8192, D=3, K=1 — single fused persistent kernel.
// d^2 = |q|^2 + (|r|^2 - 2 q.r). Work units = (qblock, chunk); each unit:
// build refmod (-2r,|r|^2) for a 128-ref chunk in SMEM, then 4 queries/thread
// vs the chunk using packed fma.rn.f32x2 over ref pairs. Grid-stride over
// units for balance at 8 CTAs/SM. Ticket epilogue does cross-chunk min + mean.

#define MREF     8192
#define NQ       32768
#define CHUNK    128
#define NCHUNK   (MREF / CHUNK)       // 64
#define TPB      128
#define QPT      4
#define QPB      (TPB * QPT)          // 512
#define QBLOCKS  (NQ / QPB)           // 64
#define UNITS    (QBLOCKS * NCHUNK)   // 4096
#define NCTA     1184                 // 148 SMs x 8 CTAs
#define STAGE2   128
#define S2_Q     (NQ / STAGE2)        // 256
#define S2_QPT   (S2_Q / TPB)         // 2

__device__ float    g_partial[NCHUNK * NQ];   // 8 MB, lives in L2
__device__ float    g_bsum[STAGE2];
__device__ unsigned g_done  = 0;
__device__ unsigned g_done2 = 0;

// ---------- packed f32x2 helpers ----------
__device__ __forceinline__ uint64_t pack_dup(float v) {
    uint64_t r;
    asm("mov.b64 %0, {%1, %1};" : "=l"(r) : "f"(v));
    return r;
}
__device__ __forceinline__ uint64_t fma2(uint64_t a, uint64_t b, uint64_t c) {
    uint64_t d;
    asm("fma.rn.f32x2 %0, %1, %2, %3;" : "=l"(d) : "l"(a), "l"(b), "l"(c));
    return d;
}
__device__ __forceinline__ void unpack2(uint64_t v, float& lo, float& hi) {
    asm("mov.b64 {%0, %1}, %2;" : "=f"(lo), "=f"(hi) : "l"(v));
}
__device__ __forceinline__ void lds_2x64(uint32_t addr, uint64_t& a, uint64_t& b) {
    asm("ld.shared.v2.b64 {%0, %1}, [%2];" : "=l"(a), "=l"(b) : "r"(addr));
}

__global__ void __launch_bounds__(TPB, 8)
chamfer_fused(const float* __restrict__ query,
              const float* __restrict__ ref,
              float* __restrict__ out) {
    __shared__ __align__(16) float s_ref[4 * CHUNK];   // x | y | z | w regions
    __shared__ float s_red[TPB];
    __shared__ unsigned s_ticket;

    const int tid = threadIdx.x;
    const uint32_t adr = (uint32_t)__cvta_generic_to_shared(s_ref);

    // ---- grid-stride over work units ----
    for (int u = blockIdx.x; u < UNITS; u += NCTA) {
        const int chunk = u >> 6;            // u / QBLOCKS
        const int qb    = u & (QBLOCKS - 1); // u % QBLOCKS

        __syncthreads();   // protect smem from previous unit's readers

        // refmod: one ref point per thread
        {
            const int m = chunk * CHUNK + tid;
            const float x = ref[3 * m + 0];
            const float y = ref[3 * m + 1];
            const float z = ref[3 * m + 2];
            s_ref[tid]             = -2.0f * x;
            s_ref[CHUNK + tid]     = -2.0f * y;
            s_ref[2 * CHUNK + tid] = -2.0f * z;
            s_ref[3 * CHUNK + tid] = x * x + y * y + z * z;
        }

        // four queries per thread (coalesced: tid + k*TPB)
        const int qbase = qb * QPB + tid;
        uint64_t pqx[QPT], pqy[QPT], pqz[QPT];
        float    q2[QPT];
        #pragma unroll
        for (int k = 0; k < QPT; k++) {
            const int q = qbase + k * TPB;
            const float x = query[3 * q + 0];
            const float y = query[3 * q + 1];
            const float z = query[3 * q + 2];
            q2[k]  = x * x + y * y + z * z;
            pqx[k] = pack_dup(x);
            pqy[k] = pack_dup(y);
            pqz[k] = pack_dup(z);
        }

        __syncthreads();

        float acc[QPT];
        #pragma unroll
        for (int k = 0; k < QPT; k++) acc[k] = CUDART_INF_F;

        // 32 iterations: 4 LDS.128 + 24 FFMA2 + 16 FMNMX -> 16 pairs/iter
        #pragma unroll 1
        for (int j = 0; j < CHUNK; j += 4) {
            const uint32_t off = adr + j * 4;
            uint64_t x01, x23, y01, y23, z01, z23, w01, w23;
            lds_2x64(off,                 x01, x23);
            lds_2x64(off + CHUNK * 4,     y01, y23);
            lds_2x64(off + 2 * CHUNK * 4, z01, z23);
            lds_2x64(off + 3 * CHUNK * 4, w01, w23);

            #pragma unroll
            for (int k = 0; k < QPT; k++) {
                uint64_t t01 = fma2(pqx[k], x01, fma2(pqy[k], y01, fma2(pqz[k], z01, w01)));
                uint64_t t23 = fma2(pqx[k], x23, fma2(pqy[k], y23, fma2(pqz[k], z23, w23)));
                float lo, hi;
                unpack2(t01, lo, hi);
                acc[k] = fminf(acc[k], fminf(lo, hi));
                unpack2(t23, lo, hi);
                acc[k] = fminf(acc[k], fminf(lo, hi));
            }
        }

        // clamp commutes with min over chunks (min is monotone)
        #pragma unroll
        for (int k = 0; k < QPT; k++) {
            g_partial[chunk * NQ + qbase + k * TPB] = fmaxf(q2[k] + acc[k], 0.0f);
        }
    }

    // ---- ticket: last STAGE2 CTAs do the global reduction ----
    __syncthreads();
    if (tid == 0) {
        __threadfence();
        s_ticket = atomicAdd(&g_done, 1u);
    }
    __syncthreads();
    const unsigned ticket = s_ticket;

    if (ticket < NCTA - STAGE2) return;

    if (tid == 0) {
        volatile unsigned* vd = &g_done;
        while (*vd < (unsigned)NCTA) { __nanosleep(64); }
    }
    __syncthreads();
    __threadfence();

    const int slice = (int)ticket - (NCTA - STAGE2);    // 0..127

    float sum = 0.0f;
    #pragma unroll
    for (int k = 0; k < S2_QPT; k++) {
        const int q = slice * S2_Q + k * TPB + tid;
        float v = g_partial[q];
        #pragma unroll
        for (int c = 1; c < NCHUNK; c++) {
            v = fminf(v, g_partial[c * NQ + q]);
        }
        sum += v;
    }
    s_red[tid] = sum;
    __syncthreads();

    #pragma unroll
    for (int stride = TPB / 2; stride >= 1; stride >>= 1) {
        if (tid < stride) s_red[tid] += s_red[tid + stride];
        __syncthreads();
    }

    if (tid == 0) {
        g_bsum[slice] = s_red[0];
        __threadfence();
        const unsigned t2 = atomicAdd(&g_done2, 1u);
        if (t2 == STAGE2 - 1) {
            __threadfence();
            float total = 0.0f;
            #pragma unroll
            for (int i = 0; i < STAGE2; i++) total += g_bsum[i];
            out[0] = total * (1.0f / (float)NQ);
            g_done  = 0u;
            g_done2 = 0u;
            __threadfence();
        }
    }
}

// ---------------------------------------------------------------------------
extern "C" void kernel_launch(void* const* d_in, const int* in_sizes, int n_in,
                              void* d_out, int out_size) {
    const float* query = (const float*)d_in[0];   // [4, 8192, 3] f32
    const float* ref   = (const float*)d_in[1];   // [8192, 3] f32
    (void)in_sizes; (void)n_in; (void)out_size;   // K == 1, fixed shapes
    float* out = (float*)d_out;

    chamfer_fused<<<NCTA, TPB>>>(query, ref, out);
}

// round 10
// speedup vs baseline: 1.6812x; 1.6812x over previous
#include <cuda_runtime.h>
#include <math_constants.h>
#include <cstdint>

// ChamferLoss: B=4, N=8192, M=8192, D=3, K=1 — single fused kernel.
// d^2 = |q|^2 + (|r|^2 - 2 q.r). Per-chunk refmod (-2r,|r|^2) in SMEM SoA.
// Inner loop: packed fma.rn.f32x2 over ref pairs, 4 queries/thread, and a
// software-pipelined double-buffered LDS prefetch (2-ref groups) so FFMA2s
// never wait a bare 29-cycle shared-load latency.

#define MREF     8192
#define NQ       32768
#define CHUNK    512
#define NCHUNK   (MREF / CHUNK)     // 16
#define TPB      128
#define QPT      4
#define QPB      (TPB * QPT)        // 512
#define QBLOCKS  (NQ / QPB)         // 64
#define GRID     (QBLOCKS * NCHUNK) // 1024
#define STAGE2   64
#define S2_Q     (NQ / STAGE2)      // 512
#define S2_QPT   (S2_Q / TPB)       // 4

#define SSTRIDE  (CHUNK + 2)        // +2 floats pad: final prefetch stays in-bounds
#define YB       (SSTRIDE * 4)      // region byte offsets
#define ZB       (2 * SSTRIDE * 4)
#define WB       (3 * SSTRIDE * 4)

__device__ float    g_partial[NCHUNK * NQ];
__device__ float    g_bsum[STAGE2];
__device__ unsigned g_done  = 0;
__device__ unsigned g_done2 = 0;

// ---------- packed f32x2 helpers ----------
__device__ __forceinline__ uint64_t pack_dup(float v) {
    uint64_t r;
    asm("mov.b64 %0, {%1, %1};" : "=l"(r) : "f"(v));
    return r;
}
__device__ __forceinline__ uint64_t fma2(uint64_t a, uint64_t b, uint64_t c) {
    uint64_t d;
    asm("fma.rn.f32x2 %0, %1, %2, %3;" : "=l"(d) : "l"(a), "l"(b), "l"(c));
    return d;
}
__device__ __forceinline__ void unpack2(uint64_t v, float& lo, float& hi) {
    asm("mov.b64 {%0, %1}, %2;" : "=f"(lo), "=f"(hi) : "l"(v));
}
__device__ __forceinline__ uint64_t lds_64(uint32_t addr) {
    uint64_t v;
    asm("ld.shared.b64 %0, [%1];" : "=l"(v) : "r"(addr));
    return v;
}

__global__ void __launch_bounds__(TPB, 7)
chamfer_fused(const float* __restrict__ query,
              const float* __restrict__ ref,
              float* __restrict__ out) {
    __shared__ __align__(16) float s_ref[4 * SSTRIDE];  // x | y | z | w regions
    __shared__ float s_red[TPB];
    __shared__ unsigned s_ticket;

    const int tid   = threadIdx.x;
    const int chunk = blockIdx.y;
    const int base  = chunk * CHUNK;

    // ---- refmod for this chunk: (-2x,-2y,-2z,|r|^2) ----
    #pragma unroll
    for (int p = 0; p < CHUNK / TPB; p++) {            // 4 points/thread
        const int i = p * TPB + tid;
        const int m = base + i;
        const float x = ref[3 * m + 0];
        const float y = ref[3 * m + 1];
        const float z = ref[3 * m + 2];
        s_ref[i]               = -2.0f * x;
        s_ref[SSTRIDE + i]     = -2.0f * y;
        s_ref[2 * SSTRIDE + i] = -2.0f * z;
        s_ref[3 * SSTRIDE + i] = x * x + y * y + z * z;
    }

    // ---- four queries per thread (coalesced: tid + k*TPB) ----
    const int qbase = blockIdx.x * QPB + tid;
    uint64_t pqx[QPT], pqy[QPT], pqz[QPT];
    float    q2[QPT];
    #pragma unroll
    for (int k = 0; k < QPT; k++) {
        const int q = qbase + k * TPB;
        const float x = query[3 * q + 0];
        const float y = query[3 * q + 1];
        const float z = query[3 * q + 2];
        q2[k]  = x * x + y * y + z * z;
        pqx[k] = pack_dup(x);
        pqy[k] = pack_dup(y);
        pqz[k] = pack_dup(z);
    }

    const uint32_t adr = (uint32_t)__cvta_generic_to_shared(s_ref);

    __syncthreads();

    // ---- pipelined main loop ----
    float acc0[QPT], acc1[QPT];
    #pragma unroll
    for (int k = 0; k < QPT; k++) { acc0[k] = CUDART_INF_F; acc1[k] = CUDART_INF_F; }

    // group = 2 refs: one u64 per coordinate
    uint64_t cx, cy, cz, cw, nx, ny, nz, nw;
    cx = lds_64(adr);
    cy = lds_64(adr + YB);
    cz = lds_64(adr + ZB);
    cw = lds_64(adr + WB);

    #pragma unroll 1
    for (int j = 0; j < CHUNK; j += 4) {
        // prefetch group j+2
        const uint32_t o2 = adr + (j + 2) * 4;
        nx = lds_64(o2);
        ny = lds_64(o2 + YB);
        nz = lds_64(o2 + ZB);
        nw = lds_64(o2 + WB);

        // compute group j (cur)
        #pragma unroll
        for (int k = 0; k < QPT; k++) {
            uint64_t t = fma2(pqz[k], cz, fma2(pqy[k], cy, fma2(pqx[k], cx, cw)));
            float lo, hi;
            unpack2(t, lo, hi);
            acc0[k] = fminf(acc0[k], lo);
            acc1[k] = fminf(acc1[k], hi);
        }

        // prefetch group j+4 (last iter reads the 2-float pad: in-bounds, unused)
        const uint32_t o4 = adr + (j + 4) * 4;
        cx = lds_64(o4);
        cy = lds_64(o4 + YB);
        cz = lds_64(o4 + ZB);
        cw = lds_64(o4 + WB);

        // compute group j+2 (nxt)
        #pragma unroll
        for (int k = 0; k < QPT; k++) {
            uint64_t t = fma2(pqz[k], nz, fma2(pqy[k], ny, fma2(pqx[k], nx, nw)));
            float lo, hi;
            unpack2(t, lo, hi);
            acc0[k] = fminf(acc0[k], lo);
            acc1[k] = fminf(acc1[k], hi);
        }
    }

    // clamp commutes with min over chunks (min is monotone)
    #pragma unroll
    for (int k = 0; k < QPT; k++) {
        const float m = fminf(acc0[k], acc1[k]);
        g_partial[chunk * NQ + qbase + k * TPB] = fmaxf(q2[k] + m, 0.0f);
    }

    // ---- ticket: last STAGE2 CTAs do the global reduction ----
    __syncthreads();
    if (tid == 0) {
        __threadfence();
        s_ticket = atomicAdd(&g_done, 1u);
    }
    __syncthreads();
    const unsigned ticket = s_ticket;

    if (ticket < GRID - STAGE2) return;

    if (tid == 0) {
        volatile unsigned* vd = &g_done;
        while (*vd < (unsigned)GRID) { __nanosleep(64); }
    }
    __syncthreads();
    __threadfence();

    const int slice = (int)ticket - (GRID - STAGE2);    // 0..63

    float sum = 0.0f;
    #pragma unroll
    for (int k = 0; k < S2_QPT; k++) {
        const int q = slice * S2_Q + k * TPB + tid;
        float v = g_partial[q];
        #pragma unroll
        for (int c = 1; c < NCHUNK; c++) {
            v = fminf(v, g_partial[c * NQ + q]);
        }
        sum += v;
    }
    s_red[tid] = sum;
    __syncthreads();

    #pragma unroll
    for (int stride = TPB / 2; stride >= 1; stride >>= 1) {
        if (tid < stride) s_red[tid] += s_red[tid + stride];
        __syncthreads();
    }

    if (tid == 0) {
        g_bsum[slice] = s_red[0];
        __threadfence();
        const unsigned t2 = atomicAdd(&g_done2, 1u);
        if (t2 == STAGE2 - 1) {
            __threadfence();
            float total = 0.0f;
            #pragma unroll
            for (int i = 0; i < STAGE2; i++) total += g_bsum[i];
            out[0] = total * (1.0f / (float)NQ);
            g_done  = 0u;
            g_done2 = 0u;
            __threadfence();
        }
    }
}

// ---------------------------------------------------------------------------
extern "C" void kernel_launch(void* const* d_in, const int* in_sizes, int n_in,
                              void* d_out, int out_size) {
    const float* query = (const float*)d_in[0];   // [4, 8192, 3] f32
    const float* ref   = (const float*)d_in[1];   // [8192, 3] f32
    (void)in_sizes; (void)n_in; (void)out_size;   // K == 1, fixed shapes
    float* out = (float*)d_out;

    chamfer_fused<<<dim3(QBLOCKS, NCHUNK), TPB>>>(query, ref, out);
}